// round 4
// baseline (speedup 1.0000x reference)
#include <cuda_runtime.h>

// RayTransform: local_pos = (pos - trans) @ R, local_dir = dir @ R
// R = exp(skew(rot_vec)) via Rodrigues. N = 16777216 rays.
// Pure HBM streaming problem: ~805 MB traffic -> target ~115 us @ ~7 TB/s.

__device__ float g_R[9];
__device__ float g_t[3];

__global__ void setup_kernel(const float* __restrict__ rot_vec,
                             const float* __restrict__ trans) {
    float x = rot_vec[0], y = rot_vec[1], z = rot_vec[2];
    float theta2 = x * x + y * y + z * z;
    float theta = sqrtf(theta2);
    float a, b;
    if (theta < 1e-8f) {
        a = 1.0f - theta2 / 6.0f;
        b = 0.5f - theta2 / 24.0f;
    } else {
        a = sinf(theta) / theta;
        b = (1.0f - cosf(theta)) / theta2;
    }
    // K = [[0,-z,y],[z,0,-x],[-y,x,0]]; R = I + a*K + b*K^2
    g_R[0] = 1.0f - b * (y * y + z * z);
    g_R[1] = -a * z + b * x * y;
    g_R[2] =  a * y + b * x * z;
    g_R[3] =  a * z + b * x * y;
    g_R[4] = 1.0f - b * (x * x + z * z);
    g_R[5] = -a * x + b * y * z;
    g_R[6] = -a * y + b * x * z;
    g_R[7] =  a * x + b * y * z;
    g_R[8] = 1.0f - b * (x * x + y * y);
    g_t[0] = trans[0];
    g_t[1] = trans[1];
    g_t[2] = trans[2];
}

// Each thread handles 4 rays = 12 floats = 3 float4 per stream.
__global__ void __launch_bounds__(256)
ray_transform_kernel(const float4* __restrict__ pos,
                     const float4* __restrict__ dir,
                     float4* __restrict__ out_pos,
                     float4* __restrict__ out_dir,
                     int ngroups) {
    int i = blockIdx.x * blockDim.x + threadIdx.x;
    if (i >= ngroups) return;

    const float R0 = g_R[0], R1 = g_R[1], R2 = g_R[2];
    const float R3 = g_R[3], R4 = g_R[4], R5 = g_R[5];
    const float R6 = g_R[6], R7 = g_R[7], R8 = g_R[8];
    const float t0 = g_t[0], t1 = g_t[1], t2 = g_t[2];

    size_t base = (size_t)i * 3;

    // ---- positions: subtract trans, then rotate ----
    {
        float4 a = pos[base];
        float4 b = pos[base + 1];
        float4 c = pos[base + 2];
        float px[4] = {a.x, a.w, b.z, c.y};
        float py[4] = {a.y, b.x, b.w, c.z};
        float pz[4] = {a.z, b.y, c.x, c.w};
        float ox[4], oy[4], oz[4];
#pragma unroll
        for (int k = 0; k < 4; k++) {
            float x = px[k] - t0;
            float y = py[k] - t1;
            float z = pz[k] - t2;
            ox[k] = fmaf(x, R0, fmaf(y, R3, z * R6));
            oy[k] = fmaf(x, R1, fmaf(y, R4, z * R7));
            oz[k] = fmaf(x, R2, fmaf(y, R5, z * R8));
        }
        out_pos[base]     = make_float4(ox[0], oy[0], oz[0], ox[1]);
        out_pos[base + 1] = make_float4(oy[1], oz[1], ox[2], oy[2]);
        out_pos[base + 2] = make_float4(oz[2], ox[3], oy[3], oz[3]);
    }

    // ---- directions: rotate only ----
    {
        float4 a = dir[base];
        float4 b = dir[base + 1];
        float4 c = dir[base + 2];
        float px[4] = {a.x, a.w, b.z, c.y};
        float py[4] = {a.y, b.x, b.w, c.z};
        float pz[4] = {a.z, b.y, c.x, c.w};
        float ox[4], oy[4], oz[4];
#pragma unroll
        for (int k = 0; k < 4; k++) {
            float x = px[k];
            float y = py[k];
            float z = pz[k];
            ox[k] = fmaf(x, R0, fmaf(y, R3, z * R6));
            oy[k] = fmaf(x, R1, fmaf(y, R4, z * R7));
            oz[k] = fmaf(x, R2, fmaf(y, R5, z * R8));
        }
        out_dir[base]     = make_float4(ox[0], oy[0], oz[0], ox[1]);
        out_dir[base + 1] = make_float4(oy[1], oz[1], ox[2], oy[2]);
        out_dir[base + 2] = make_float4(oz[2], ox[3], oy[3], oz[3]);
    }
}

extern "C" void kernel_launch(void* const* d_in, const int* in_sizes, int n_in,
                              void* d_out, int out_size) {
    const float* pos = (const float*)d_in[0];      // [N,3]
    const float* dir = (const float*)d_in[1];      // [N,3]
    const float* rot_vec = (const float*)d_in[2];  // [3]
    const float* trans = (const float*)d_in[3];    // [3]

    int n = in_sizes[0] / 3;  // number of rays
    float* out = (float*)d_out;
    float* out_pos = out;                      // first N*3 floats
    float* out_dir = out + (size_t)out_size / 2;  // second N*3 floats

    setup_kernel<<<1, 1>>>(rot_vec, trans);

    int ngroups = n / 4;  // 4 rays (3 float4) per thread; N divisible by 4
    int threads = 256;
    int blocks = (ngroups + threads - 1) / threads;
    ray_transform_kernel<<<blocks, threads>>>(
        (const float4*)pos, (const float4*)dir,
        (float4*)out_pos, (float4*)out_dir, ngroups);
}

// round 5
// speedup vs baseline: 1.1716x; 1.1716x over previous
#include <cuda_runtime.h>

// RayTransform: local_pos = (pos - trans) @ R, local_dir = dir @ R
// R = exp(skew(rot_vec)) via Rodrigues. N = 16777216 rays.
// HBM streaming: ~805 MB traffic. Strategy: smem-staged transpose so ALL
// gmem traffic is perfectly coalesced float4 (4 sectors per warp request),
// conflict-free stride-12-word smem access, R computed per block (no setup
// kernel launch).

#define THREADS 256
#define F4_PER_STREAM (THREADS * 3)  // 768 float4 tile per stream per block

__global__ void __launch_bounds__(THREADS)
ray_transform_kernel(const float4* __restrict__ pos,
                     const float4* __restrict__ dir,
                     float4* __restrict__ out_pos,
                     float4* __restrict__ out_dir,
                     const float* __restrict__ rot_vec,
                     const float* __restrict__ trans) {
    __shared__ float4 bufp[F4_PER_STREAM];
    __shared__ float4 bufd[F4_PER_STREAM];
    __shared__ float sR[12];

    const int t = threadIdx.x;
    const size_t gbase = (size_t)blockIdx.x * F4_PER_STREAM;

    // ---- coalesced loads, all 6 in flight (MLP=6) ----
    float4 p0 = pos[gbase + t];
    float4 p1 = pos[gbase + t + THREADS];
    float4 p2 = pos[gbase + t + 2 * THREADS];
    float4 d0 = dir[gbase + t];
    float4 d1 = dir[gbase + t + THREADS];
    float4 d2 = dir[gbase + t + 2 * THREADS];

    if (t == 0) {
        float x = rot_vec[0], y = rot_vec[1], z = rot_vec[2];
        float theta2 = x * x + y * y + z * z;
        float theta = sqrtf(theta2);
        float a, b;
        if (theta < 1e-8f) {
            a = 1.0f - theta2 / 6.0f;
            b = 0.5f - theta2 / 24.0f;
        } else {
            a = sinf(theta) / theta;
            b = (1.0f - cosf(theta)) / theta2;
        }
        sR[0] = 1.0f - b * (y * y + z * z);
        sR[1] = -a * z + b * x * y;
        sR[2] =  a * y + b * x * z;
        sR[3] =  a * z + b * x * y;
        sR[4] = 1.0f - b * (x * x + z * z);
        sR[5] = -a * x + b * y * z;
        sR[6] = -a * y + b * x * z;
        sR[7] =  a * x + b * y * z;
        sR[8] = 1.0f - b * (x * x + y * y);
        sR[9]  = trans[0];
        sR[10] = trans[1];
        sR[11] = trans[2];
    }

    bufp[t] = p0;
    bufp[t + THREADS] = p1;
    bufp[t + 2 * THREADS] = p2;
    bufd[t] = d0;
    bufd[t + THREADS] = d1;
    bufd[t + 2 * THREADS] = d2;
    __syncthreads();  // covers smem tiles AND sR

    const float R0 = sR[0], R1 = sR[1], R2 = sR[2];
    const float R3 = sR[3], R4 = sR[4], R5 = sR[5];
    const float R6 = sR[6], R7 = sR[7], R8 = sR[8];
    const float t0 = sR[9], t1 = sR[10], t2 = sR[11];

    // Per-thread view: thread t owns float4s 3t..3t+2 (4 rays).
    // Word stride 12: (12t) mod 32 distinct within each 8-lane LDS.128 phase
    // -> conflict-free. Read/modify/write is same-thread-same-address, so no
    // barrier needed between the read and the write-back.
    {
        float4 a = bufp[t * 3], b = bufp[t * 3 + 1], c = bufp[t * 3 + 2];
        float px[4] = {a.x, a.w, b.z, c.y};
        float py[4] = {a.y, b.x, b.w, c.z};
        float pz[4] = {a.z, b.y, c.x, c.w};
        float ox[4], oy[4], oz[4];
#pragma unroll
        for (int k = 0; k < 4; k++) {
            float x = px[k] - t0;
            float y = py[k] - t1;
            float z = pz[k] - t2;
            ox[k] = fmaf(x, R0, fmaf(y, R3, z * R6));
            oy[k] = fmaf(x, R1, fmaf(y, R4, z * R7));
            oz[k] = fmaf(x, R2, fmaf(y, R5, z * R8));
        }
        bufp[t * 3]     = make_float4(ox[0], oy[0], oz[0], ox[1]);
        bufp[t * 3 + 1] = make_float4(oy[1], oz[1], ox[2], oy[2]);
        bufp[t * 3 + 2] = make_float4(oz[2], ox[3], oy[3], oz[3]);
    }
    {
        float4 a = bufd[t * 3], b = bufd[t * 3 + 1], c = bufd[t * 3 + 2];
        float px[4] = {a.x, a.w, b.z, c.y};
        float py[4] = {a.y, b.x, b.w, c.z};
        float pz[4] = {a.z, b.y, c.x, c.w};
        float ox[4], oy[4], oz[4];
#pragma unroll
        for (int k = 0; k < 4; k++) {
            float x = px[k];
            float y = py[k];
            float z = pz[k];
            ox[k] = fmaf(x, R0, fmaf(y, R3, z * R6));
            oy[k] = fmaf(x, R1, fmaf(y, R4, z * R7));
            oz[k] = fmaf(x, R2, fmaf(y, R5, z * R8));
        }
        bufd[t * 3]     = make_float4(ox[0], oy[0], oz[0], ox[1]);
        bufd[t * 3 + 1] = make_float4(oy[1], oz[1], ox[2], oy[2]);
        bufd[t * 3 + 2] = make_float4(oz[2], ox[3], oy[3], oz[3]);
    }
    __syncthreads();  // per-thread writes -> cross-thread coalesced reads

    // ---- coalesced stores ----
    out_pos[gbase + t]               = bufp[t];
    out_pos[gbase + t + THREADS]     = bufp[t + THREADS];
    out_pos[gbase + t + 2 * THREADS] = bufp[t + 2 * THREADS];
    out_dir[gbase + t]               = bufd[t];
    out_dir[gbase + t + THREADS]     = bufd[t + THREADS];
    out_dir[gbase + t + 2 * THREADS] = bufd[t + 2 * THREADS];
}

extern "C" void kernel_launch(void* const* d_in, const int* in_sizes, int n_in,
                              void* d_out, int out_size) {
    const float* pos = (const float*)d_in[0];      // [N,3]
    const float* dir = (const float*)d_in[1];      // [N,3]
    const float* rot_vec = (const float*)d_in[2];  // [3]
    const float* trans = (const float*)d_in[3];    // [3]

    int n_f4 = in_sizes[0] / 4;  // N*3/4 float4 per stream (N*3 divisible by 4)
    float* out = (float*)d_out;
    float* out_pos = out;
    float* out_dir = out + (size_t)out_size / 2;

    int blocks = n_f4 / F4_PER_STREAM;  // 12582912 / 768 = 16384, exact
    ray_transform_kernel<<<blocks, THREADS>>>(
        (const float4*)pos, (const float4*)dir,
        (float4*)out_pos, (float4*)out_dir, rot_vec, trans);
}

// round 7
// speedup vs baseline: 1.1725x; 1.0008x over previous
#include <cuda_runtime.h>

// RayTransform: local_pos = (pos - trans) @ R, local_dir = dir @ R
// R = exp(skew(rot_vec)) via Rodrigues. N = 16777216 rays.
// HBM streaming ~805 MB. Each block processes ONE 768-float4 tile of ONE
// stream (pos or dir) -> half the smem (12.3KB) and register state of the
// fused version, double the block count (32768) for finer latency overlap.
// All gmem traffic coalesced float4; smem transpose is conflict-free
// (stride 12 words).

#define THREADS 256
#define F4_PER_TILE (THREADS * 3)  // 768 float4 per tile

__global__ void __launch_bounds__(THREADS, 6)
ray_transform_kernel(const float4* __restrict__ pos,
                     const float4* __restrict__ dir,
                     float4* __restrict__ out_pos,
                     float4* __restrict__ out_dir,
                     const float* __restrict__ rot_vec,
                     const float* __restrict__ trans,
                     int nblocks_per_stream) {
    __shared__ float4 buf[F4_PER_TILE];
    __shared__ float sR[12];

    const int t = threadIdx.x;
    const int bid = blockIdx.x;
    const bool is_pos = bid < nblocks_per_stream;
    const int tile = is_pos ? bid : (bid - nblocks_per_stream);

    const float4* __restrict__ in = is_pos ? pos : dir;
    float4* __restrict__ outp = is_pos ? out_pos : out_dir;
    const size_t gbase = (size_t)tile * F4_PER_TILE;

    // coalesced loads (3 LDG.128 in flight)
    float4 v0 = in[gbase + t];
    float4 v1 = in[gbase + t + THREADS];
    float4 v2 = in[gbase + t + 2 * THREADS];

    if (t == 0) {
        float x = rot_vec[0], y = rot_vec[1], z = rot_vec[2];
        float theta2 = x * x + y * y + z * z;
        float theta = sqrtf(theta2);
        float a, b;
        if (theta < 1e-8f) {
            a = 1.0f - theta2 / 6.0f;
            b = 0.5f - theta2 / 24.0f;
        } else {
            a = sinf(theta) / theta;
            b = (1.0f - cosf(theta)) / theta2;
        }
        sR[0] = 1.0f - b * (y * y + z * z);
        sR[1] = -a * z + b * x * y;
        sR[2] =  a * y + b * x * z;
        sR[3] =  a * z + b * x * y;
        sR[4] = 1.0f - b * (x * x + z * z);
        sR[5] = -a * x + b * y * z;
        sR[6] = -a * y + b * x * z;
        sR[7] =  a * x + b * y * z;
        sR[8] = 1.0f - b * (x * x + y * y);
        // translation: only pos blocks subtract; dir blocks use 0
        sR[9]  = trans[0];
        sR[10] = trans[1];
        sR[11] = trans[2];
    }

    buf[t] = v0;
    buf[t + THREADS] = v1;
    buf[t + 2 * THREADS] = v2;
    __syncthreads();  // covers tile AND sR

    const float R0 = sR[0], R1 = sR[1], R2 = sR[2];
    const float R3 = sR[3], R4 = sR[4], R5 = sR[5];
    const float R6 = sR[6], R7 = sR[7], R8 = sR[8];
    const float t0 = is_pos ? sR[9]  : 0.0f;
    const float t1 = is_pos ? sR[10] : 0.0f;
    const float t2 = is_pos ? sR[11] : 0.0f;

    // Thread t owns float4s 3t..3t+2 (4 rays). Word stride 12 is
    // conflict-free for LDS/STS.128. Same-thread read-modify-write: no
    // barrier needed between read and write-back.
    {
        float4 a = buf[t * 3], b = buf[t * 3 + 1], c = buf[t * 3 + 2];
        float px[4] = {a.x, a.w, b.z, c.y};
        float py[4] = {a.y, b.x, b.w, c.z};
        float pz[4] = {a.z, b.y, c.x, c.w};
        float ox[4], oy[4], oz[4];
#pragma unroll
        for (int k = 0; k < 4; k++) {
            float x = px[k] - t0;
            float y = py[k] - t1;
            float z = pz[k] - t2;
            ox[k] = fmaf(x, R0, fmaf(y, R3, z * R6));
            oy[k] = fmaf(x, R1, fmaf(y, R4, z * R7));
            oz[k] = fmaf(x, R2, fmaf(y, R5, z * R8));
        }
        buf[t * 3]     = make_float4(ox[0], oy[0], oz[0], ox[1]);
        buf[t * 3 + 1] = make_float4(oy[1], oz[1], ox[2], oy[2]);
        buf[t * 3 + 2] = make_float4(oz[2], ox[3], oy[3], oz[3]);
    }
    __syncthreads();  // per-thread writes -> cross-thread coalesced reads

    // coalesced stores
    outp[gbase + t]               = buf[t];
    outp[gbase + t + THREADS]     = buf[t + THREADS];
    outp[gbase + t + 2 * THREADS] = buf[t + 2 * THREADS];
}

extern "C" void kernel_launch(void* const* d_in, const int* in_sizes, int n_in,
                              void* d_out, int out_size) {
    const float* pos = (const float*)d_in[0];      // [N,3]
    const float* dir = (const float*)d_in[1];      // [N,3]
    const float* rot_vec = (const float*)d_in[2];  // [3]
    const float* trans = (const float*)d_in[3];    // [3]

    int n_f4 = in_sizes[0] / 4;  // N*3/4 float4 per stream
    float* out = (float*)d_out;
    float* out_pos = out;
    float* out_dir = out + (size_t)out_size / 2;

    int nblocks_per_stream = n_f4 / F4_PER_TILE;  // 12582912/768 = 16384, exact
    int blocks = nblocks_per_stream * 2;
    ray_transform_kernel<<<blocks, THREADS>>>(
        (const float4*)pos, (const float4*)dir,
        (float4*)out_pos, (float4*)out_dir, rot_vec, trans,
        nblocks_per_stream);
}